// round 16
// baseline (speedup 1.0000x reference)
#include <cuda_runtime.h>
#include <cuda_fp16.h>
#include <cstdint>
#include <math.h>

// Problem constants
#define BATCH 2
#define SEQ 2048
#define DMODEL 4096
#define NHEAD 32
#define NKVHEAD 8
#define DHEAD 128
#define MROWS (BATCH * SEQ)            // 4096
#define QCOLS (NHEAD * DHEAD)          // 4096
#define KVCOLS (NKVHEAD * DHEAD)       // 1024
#define QKVCOLS (QCOLS + 2 * KVCOLS)   // 6144

// ---------------------------------------------------------------------------
// Scratch buffers (__device__ globals; allocation-free rule)
// ---------------------------------------------------------------------------
__device__ __half X16[(size_t)MROWS * DMODEL];
__device__ __half WQKVT16[(size_t)QKVCOLS * DMODEL];  // rows: 0-4095 Q, 4096-5119 K, 5120-6143 V
__device__ __half WOT16[(size_t)DMODEL * DMODEL];
__device__ __half Z16[(size_t)MROWS * DMODEL];
__device__ __half Q16[(size_t)MROWS * QCOLS];
__device__ __half K16[(size_t)MROWS * KVCOLS];
__device__ __half V16[(size_t)MROWS * KVCOLS];

// ---------------------------------------------------------------------------
// Helpers
// ---------------------------------------------------------------------------
__device__ __forceinline__ uint32_t smem_u32(const void* p) {
    uint32_t a;
    asm("{ .reg .u64 t; cvta.to.shared.u64 t, %1; cvt.u32.u64 %0, t; }" : "=r"(a) : "l"(p));
    return a;
}

__device__ __forceinline__ void cp16(uint32_t dst, const void* src) {
    asm volatile("cp.async.cg.shared.global [%0], [%1], 16;" :: "r"(dst), "l"(src));
}
#define CP_COMMIT() asm volatile("cp.async.commit_group;" ::: "memory")
template <int N>
__device__ __forceinline__ void cp_wait() {
    asm volatile("cp.async.wait_group %0;" :: "n"(N) : "memory");
}

#define LDSM4(r, addr)                                                        \
    asm volatile("ldmatrix.sync.aligned.m8n8.x4.shared.b16 {%0,%1,%2,%3}, [%4];" \
        : "=r"((r)[0]), "=r"((r)[1]), "=r"((r)[2]), "=r"((r)[3]) : "r"(addr))

#define LDSM4T(r, addr)                                                       \
    asm volatile("ldmatrix.sync.aligned.m8n8.x4.trans.shared.b16 {%0,%1,%2,%3}, [%4];" \
        : "=r"((r)[0]), "=r"((r)[1]), "=r"((r)[2]), "=r"((r)[3]) : "r"(addr))

#define MMAH(c, a, b0, b1)                                                    \
    asm volatile("mma.sync.aligned.m16n8k16.row.col.f32.f16.f16.f32 "         \
        "{%0,%1,%2,%3}, {%4,%5,%6,%7}, {%8,%9}, {%0,%1,%2,%3};"               \
        : "+f"((c)[0]), "+f"((c)[1]), "+f"((c)[2]), "+f"((c)[3])              \
        : "r"((a)[0]), "r"((a)[1]), "r"((a)[2]), "r"((a)[3]),                 \
          "r"(b0), "r"(b1))

__device__ __forceinline__ uint32_t packh2(float x, float y) {
    __half2 h = __floats2half2_rn(x, y);
    return *(uint32_t*)&h;
}

// swizzled byte offset within a 64B-row tile for (row, kseg[0..3])
__device__ __forceinline__ uint32_t swz_off(int row, int ks) {
    return (uint32_t)(row * 64 + (((ks ^ (row >> 1)) & 3) << 4));
}

// ---------------------------------------------------------------------------
// prep_all: one launch: x fp32->fp16 convert + all 4 weight transposes.
// ---------------------------------------------------------------------------
#define X_JOBS 2048
#define WT_Q (64 * 128)
#define WT_K (64 * 32)
#define WT_V WT_K
#define WT_O (64 * 128)
#define PREP_JOBS (X_JOBS + WT_Q + WT_K + WT_V + WT_O)

__global__ __launch_bounds__(256) void prep_all(const float* __restrict__ x,
                                                const float* __restrict__ wq,
                                                const float* __restrict__ wk,
                                                const float* __restrict__ wv,
                                                const float* __restrict__ wo,
                                                __half* __restrict__ x16,
                                                __half* __restrict__ wqkv,
                                                __half* __restrict__ wot) {
    __shared__ float t[64][33];
    const int tid = threadIdx.x;
    int id = blockIdx.x;

    if (id < X_JOBS) {
        const float4* src = (const float4*)x + (size_t)id * 2048;
        uint4* dst = (uint4*)x16 + (size_t)id * 1024;
        #pragma unroll
        for (int u = 0; u < 4; u++) {
            int p = tid + u * 256;
            float4 a = src[2 * p];
            float4 b = src[2 * p + 1];
            uint4 o;
            o.x = packh2(a.x, a.y);
            o.y = packh2(a.z, a.w);
            o.z = packh2(b.x, b.y);
            o.w = packh2(b.z, b.w);
            dst[p] = o;
        }
        return;
    }
    id -= X_JOBS;

    const float* W;
    __half* T;
    int N;
    if (id < WT_Q)                { W = wq; T = wqkv;                                     N = QCOLS;  }
    else if (id < WT_Q + WT_K)    { W = wk; T = wqkv + (size_t)QCOLS * DMODEL;            N = KVCOLS; id -= WT_Q; }
    else if (id < WT_Q + WT_K + WT_V) { W = wv; T = wqkv + (size_t)(QCOLS + KVCOLS) * DMODEL; N = KVCOLS; id -= WT_Q + WT_K; }
    else                          { W = wo; T = wot;                                      N = DMODEL; id -= WT_Q + WT_K + WT_V; }

    const int ntx = N / 32;
    const int n0 = (id % ntx) * 32;
    const int k0 = (id / ntx) * 64;

    #pragma unroll
    for (int u = 0; u < 8; u++) {
        int idx = tid + u * 256;
        int row = idx >> 5, col = idx & 31;
        t[row][col] = W[(size_t)(k0 + row) * N + n0 + col];
    }
    __syncthreads();

    const int w = tid >> 5, lane = tid & 31;
    #pragma unroll
    for (int rr = 0; rr < 4; rr++) {
        int n = n0 + w * 4 + rr;
        __half2 v = __floats2half2_rn(t[lane * 2][w * 4 + rr],
                                      t[lane * 2 + 1][w * 4 + rr]);
        *(__half2*)(T + (size_t)n * DMODEL + k0 + lane * 2) = v;
    }
}

// ---------------------------------------------------------------------------
// GEMM config (R13): 256 threads, 8 warps (2x4), warp tile 64x32,
// BM=128, BN=128, BK=64/stage, NST=3, 98KB smem, 2 CTAs/SM.
// ---------------------------------------------------------------------------
#define BM 128
#define A32_B (BM * 32 * 2)                 // 8192
#define GBN 128
#define B32_B (GBN * 32 * 2)                // 8192
#define G_STAGE (2 * A32_B + 2 * B32_B)     // 32768
#define G_NST 3
#define GEMM_SMEM (G_NST * G_STAGE)         // 98304

// ---------------------------------------------------------------------------
// Merged QKV single-pass fp16 GEMM, fused RoPE/scale/head-major epilogue.
// grid (48, 32) = 1536 CTAs; 2 CTAs/SM.
// ---------------------------------------------------------------------------
__global__ __launch_bounds__(256, 2)
void gemm_qkv(const __half* __restrict__ A, const __half* __restrict__ B,
              const float* __restrict__ cosb, const float* __restrict__ sinb,
              __half* __restrict__ qo, __half* __restrict__ ko,
              __half* __restrict__ vo, float qs) {
    extern __shared__ char smem[];
    const uint32_t sb = smem_u32(smem);
    const int tid = threadIdx.x;
    const int wid = tid >> 5;
    const int lane = tid & 31;
    const int wm = wid >> 2;
    const int wn = wid & 3;
    const int m0 = blockIdx.y * BM;
    const int n0 = blockIdx.x * GBN;
    const int K = DMODEL;
    const int TOT = K / 64;

    float acc[4][4][4];
    #pragma unroll
    for (int i = 0; i < 4; i++)
        #pragma unroll
        for (int j = 0; j < 4; j++)
            #pragma unroll
            for (int r = 0; r < 4; r++) acc[i][j][r] = 0.0f;

    auto load_chunk = [&](int c, int s) {
        const __half* as = A + (size_t)m0 * K + c * 64;
        const __half* bs = B + (size_t)n0 * K + c * 64;
        uint32_t base = sb + s * G_STAGE;
        #pragma unroll
        for (int t = 0; t < 8; t++) {
            int idx = tid + t * 256;
            if (idx < 1024) {
                int kh = idx >> 9;
                int j = idx & 511;
                int row = j >> 2, ks = j & 3;
                cp16(base + kh * A32_B + swz_off(row, ks),
                     as + kh * 32 + (size_t)row * K + ks * 8);
            } else {
                int j = idx - 1024;
                int kh = j >> 9;
                int jj = j & 511;
                int row = jj >> 2, ks = jj & 3;
                cp16(base + 2 * A32_B + kh * B32_B + swz_off(row, ks),
                     bs + kh * 32 + (size_t)row * K + ks * 8);
            }
        }
    };

    load_chunk(0, 0); CP_COMMIT();
    load_chunk(1, 1); CP_COMMIT();

    const int r15 = lane & 15;
    const int hsel = lane >> 4;

    for (int c = 0; c < TOT; c++) {
        const int s = c % G_NST;
        cp_wait<1>();
        __syncthreads();

        {
            int nc = c + 2;
            if (nc < TOT) load_chunk(nc, nc % G_NST);
            CP_COMMIT();
        }

        const uint32_t ab0 = sb + s * G_STAGE;
        const uint32_t bb0 = ab0 + 2 * A32_B;

        #pragma unroll
        for (int kh = 0; kh < 2; kh++) {
            const uint32_t ab = ab0 + kh * A32_B;
            const uint32_t bb = bb0 + kh * B32_B;
            #pragma unroll
            for (int ks2 = 0; ks2 < 2; ks2++) {
                const int kseg = ks2 * 2 + hsel;
                uint32_t aF[4][4], bF[2][4];
                #pragma unroll
                for (int i = 0; i < 4; i++)
                    LDSM4(aF[i], ab + swz_off(wm * 64 + i * 16 + r15, kseg));
                #pragma unroll
                for (int j = 0; j < 2; j++)
                    LDSM4(bF[j], bb + swz_off(wn * 32 + j * 16 + r15, kseg));
                #pragma unroll
                for (int i = 0; i < 4; i++)
                    #pragma unroll
                    for (int j = 0; j < 2; j++) {
                        MMAH(acc[i][2 * j],     aF[i], bF[j][0], bF[j][2]);
                        MMAH(acc[i][2 * j + 1], aF[i], bF[j][1], bF[j][3]);
                    }
            }
        }
    }

    // Fused epilogue: CTA column block -> single head/region.
    const int quad = lane >> 2;
    const int tq = lane & 3;
    __half* dst;
    int H, c0;
    bool dorope;
    float scl;
    if (n0 < QCOLS)            { dst = qo; H = NHEAD;   c0 = n0;                 dorope = true;  scl = qs; }
    else if (n0 < QCOLS + 1024){ dst = ko; H = NKVHEAD; c0 = n0 - QCOLS;         dorope = true;  scl = 1.0f; }
    else                       { dst = vo; H = NKVHEAD; c0 = n0 - QCOLS - 1024;  dorope = false; scl = 1.0f; }
    const int h = c0 >> 7;

    #pragma unroll
    for (int i = 0; i < 4; i++) {
        int r0 = m0 + wm * 64 + i * 16 + quad;
        int b0 = r0 >> 11;
        int t0 = r0 & (SEQ - 1);
        #pragma unroll
        for (int j = 0; j < 4; j++) {
            int d = wn * 32 + j * 8 + tq * 2;
            int d2 = d >> 1;
            float f0 = acc[i][j][0], f1 = acc[i][j][1];
            float f2 = acc[i][j][2], f3 = acc[i][j][3];
            if (dorope) {
                float c0v = cosb[t0 * 64 + d2], s0v = sinb[t0 * 64 + d2];
                float c1v = cosb[(t0 + 8) * 64 + d2], s1v = sinb[(t0 + 8) * 64 + d2];
                float a0 = (f0 * c0v - f1 * s0v) * scl, a1 = (f0 * s0v + f1 * c0v) * scl;
                float a2 = (f2 * c1v - f3 * s1v) * scl, a3 = (f2 * s1v + f3 * c1v) * scl;
                f0 = a0; f1 = a1; f2 = a2; f3 = a3;
            }
            size_t o0 = (((size_t)b0 * H + h) * SEQ + t0) * DHEAD + d;
            *(__half2*)(dst + o0) = __floats2half2_rn(f0, f1);
            *(__half2*)(dst + o0 + (size_t)8 * DHEAD) = __floats2half2_rn(f2, f3);
        }
    }
}

// ---------------------------------------------------------------------------
// WO projection: single-pass fp16 GEMM (R13 config). 1024 CTAs.
// ---------------------------------------------------------------------------
__global__ __launch_bounds__(256, 2)
void wo_gemm(const __half* __restrict__ A, const __half* __restrict__ B,
             float* __restrict__ C, int N, int K) {
    extern __shared__ char smem[];
    const uint32_t sb = smem_u32(smem);
    const int tid = threadIdx.x;
    const int wid = tid >> 5;
    const int lane = tid & 31;
    const int wm = wid >> 2;
    const int wn = wid & 3;
    const int m0 = blockIdx.y * BM;
    const int n0 = blockIdx.x * GBN;
    const int TOT = K / 64;

    float acc[4][4][4];
    #pragma unroll
    for (int i = 0; i < 4; i++)
        #pragma unroll
        for (int j = 0; j < 4; j++)
            #pragma unroll
            for (int r = 0; r < 4; r++) acc[i][j][r] = 0.0f;

    auto load_chunk = [&](int c, int s) {
        const __half* as = A + (size_t)m0 * K + c * 64;
        const __half* bs = B + (size_t)n0 * K + c * 64;
        uint32_t base = sb + s * G_STAGE;
        #pragma unroll
        for (int t = 0; t < 8; t++) {
            int idx = tid + t * 256;
            if (idx < 1024) {
                int kh = idx >> 9;
                int j = idx & 511;
                int row = j >> 2, ks = j & 3;
                cp16(base + kh * A32_B + swz_off(row, ks),
                     as + kh * 32 + (size_t)row * K + ks * 8);
            } else {
                int j = idx - 1024;
                int kh = j >> 9;
                int jj = j & 511;
                int row = jj >> 2, ks = jj & 3;
                cp16(base + 2 * A32_B + kh * B32_B + swz_off(row, ks),
                     bs + kh * 32 + (size_t)row * K + ks * 8);
            }
        }
    };

    load_chunk(0, 0); CP_COMMIT();
    load_chunk(1, 1); CP_COMMIT();

    const int r15 = lane & 15;
    const int hsel = lane >> 4;

    for (int c = 0; c < TOT; c++) {
        const int s = c % G_NST;
        cp_wait<1>();
        __syncthreads();

        {
            int nc = c + 2;
            if (nc < TOT) load_chunk(nc, nc % G_NST);
            CP_COMMIT();
        }

        const uint32_t ab0 = sb + s * G_STAGE;
        const uint32_t bb0 = ab0 + 2 * A32_B;

        #pragma unroll
        for (int kh = 0; kh < 2; kh++) {
            const uint32_t ab = ab0 + kh * A32_B;
            const uint32_t bb = bb0 + kh * B32_B;
            #pragma unroll
            for (int ks2 = 0; ks2 < 2; ks2++) {
                const int kseg = ks2 * 2 + hsel;
                uint32_t aF[4][4], bF[2][4];
                #pragma unroll
                for (int i = 0; i < 4; i++)
                    LDSM4(aF[i], ab + swz_off(wm * 64 + i * 16 + r15, kseg));
                #pragma unroll
                for (int j = 0; j < 2; j++)
                    LDSM4(bF[j], bb + swz_off(wn * 32 + j * 16 + r15, kseg));
                #pragma unroll
                for (int i = 0; i < 4; i++)
                    #pragma unroll
                    for (int j = 0; j < 2; j++) {
                        MMAH(acc[i][2 * j],     aF[i], bF[j][0], bF[j][2]);
                        MMAH(acc[i][2 * j + 1], aF[i], bF[j][1], bF[j][3]);
                    }
            }
        }
    }

    const int quad = lane >> 2;
    const int tq = lane & 3;
    #pragma unroll
    for (int i = 0; i < 4; i++) {
        int row0 = m0 + wm * 64 + i * 16 + quad;
        #pragma unroll
        for (int j = 0; j < 4; j++) {
            int col = n0 + wn * 32 + j * 8 + tq * 2;
            *(float2*)(C + (size_t)row0 * N + col) =
                make_float2(acc[i][j][0], acc[i][j][1]);
            *(float2*)(C + (size_t)(row0 + 8) * N + col) =
                make_float2(acc[i][j][2], acc[i][j][3]);
        }
    }
}

// ----------------------------------------------------------------------------
// HMMA fp16 flash attention. KV tiles 128 wide; heavy q-tiles first.
// 3-stage KV ring: one __syncthreads per tile, 2 KV tiles in flight.
// smem = 32KB Q + 3*64KB KV = 224KB.
// ----------------------------------------------------------------------------
#define QS_BYTES (128 * 128 * 2)
#define KV_BYTES (128 * 128 * 2)
#define FL_NST 3
#define FLASH_SMEM (QS_BYTES + FL_NST * (2 * KV_BYTES))   // 229376

__global__ __launch_bounds__(256, 1)
void flash_hmma(const __half* __restrict__ Qg, const __half* __restrict__ Kg,
                const __half* __restrict__ Vg, __half* __restrict__ Z) {
    extern __shared__ char smem[];
    const uint32_t sb = smem_u32(smem);
    const int tid = threadIdx.x;
    const int wid = tid >> 5;
    const int lane = tid & 31;
    const int quad = lane >> 2, tq = lane & 3;
    const int r15 = lane & 15, hsel = lane >> 4;
    const int qt = (gridDim.x - 1) - blockIdx.x;
    const int q0 = qt * 128;
    const int bh = blockIdx.y;
    const int b = bh >> 5, h = bh & 31, kvh = h >> 2;
    const __half* qsrc = Qg + ((size_t)bh * SEQ + q0) * DHEAD;
    const __half* ksrc0 = Kg + ((size_t)(b * NKVHEAD + kvh)) * SEQ * DHEAD;
    const __half* vsrc0 = Vg + ((size_t)(b * NKVHEAD + kvh)) * SEQ * DHEAD;
    const int nkt = qt + 1;

    #pragma unroll
    for (int t = 0; t < 8; t++) {
        int j = tid + t * 256;
        int row = j >> 4, dc = (j >> 2) & 3, ks = j & 3;
        cp16(sb + dc * 8192 + swz_off(row, ks), qsrc + (size_t)row * DHEAD + dc * 32 + ks * 8);
    }
    CP_COMMIT();

    auto load_kv = [&](int t, int s) {
        uint32_t kb = sb + QS_BYTES + s * (2 * KV_BYTES);
        uint32_t vb = kb + KV_BYTES;
        const __half* ks_ = ksrc0 + (size_t)t * 128 * DHEAD;
        const __half* vs_ = vsrc0 + (size_t)t * 128 * DHEAD;
        #pragma unroll
        for (int u = 0; u < 16; u++) {
            int j = tid + u * 256;
            bool isv = j >= 2048;
            int jj = j & 2047;
            int row = jj >> 4, dc = (jj >> 2) & 3, ks = jj & 3;
            cp16((isv ? vb : kb) + dc * 8192 + swz_off(row, ks),
                 (isv ? vs_ : ks_) + (size_t)row * DHEAD + dc * 32 + ks * 8);
        }
    };

    load_kv(0, 0); CP_COMMIT();
    cp_wait<1>();          // Q resident (kv0 may still be in flight)
    __syncthreads();

    uint32_t qF[8][4];
    #pragma unroll
    for (int kc = 0; kc < 8; kc++) {
        int dc = kc >> 1;
        LDSM4(qF[kc], sb + dc * 8192 + swz_off(wid * 16 + r15, (kc & 1) * 2 + hsel));
    }

    if (nkt > 1) load_kv(1, 1);
    CP_COMMIT();

    float o[16][4];
    #pragma unroll
    for (int i = 0; i < 16; i++)
        #pragma unroll
        for (int r = 0; r < 4; r++) o[i][r] = 0.0f;
    float m0v = -1e30f, m1v = -1e30f, l0v = 0.0f, l1v = 0.0f;

    const int row_g0 = q0 + wid * 16 + quad;

    for (int t = 0; t < nkt; t++) {
        cp_wait<1>();          // kv(t) resident; kv(t+1) may be in flight
        __syncthreads();       // all warps done with stage (t+2)%3 (tile t-1)

        // issue kv(t+2) into the free ring slot before compute
        if (t + 2 < nkt) load_kv(t + 2, (t + 2) % FL_NST);
        CP_COMMIT();

        const uint32_t kb = sb + QS_BYTES + (t % FL_NST) * (2 * KV_BYTES);
        const uint32_t vb = kb + KV_BYTES;

        float s[16][4];
        #pragma unroll
        for (int j = 0; j < 16; j++)
            #pragma unroll
            for (int r = 0; r < 4; r++) s[j][r] = 0.0f;

        #pragma unroll
        for (int kc = 0; kc < 8; kc++) {
            int dc = kc >> 1;
            #pragma unroll
            for (int j = 0; j < 8; j++) {
                uint32_t kf[4];
                LDSM4(kf, kb + dc * 8192 + swz_off(j * 16 + r15, (kc & 1) * 2 + hsel));
                MMAH(s[2 * j],     qF[kc], kf[0], kf[2]);
                MMAH(s[2 * j + 1], qF[kc], kf[1], kf[3]);
            }
        }

        if (t == nkt - 1) {
            #pragma unroll
            for (int j = 0; j < 16; j++) {
                int col = t * 128 + j * 8 + tq * 2;
                if (col     > row_g0)     s[j][0] = -1e30f;
                if (col + 1 > row_g0)     s[j][1] = -1e30f;
                if (col     > row_g0 + 8) s[j][2] = -1e30f;
                if (col + 1 > row_g0 + 8) s[j][3] = -1e30f;
            }
        }

        float rm0 = -1e30f, rm1 = -1e30f;
        #pragma unroll
        for (int j = 0; j < 16; j++) {
            rm0 = fmaxf(rm0, fmaxf(s[j][0], s[j][1]));
            rm1 = fmaxf(rm1, fmaxf(s[j][2], s[j][3]));
        }
        rm0 = fmaxf(rm0, __shfl_xor_sync(0xffffffffu, rm0, 1));
        rm0 = fmaxf(rm0, __shfl_xor_sync(0xffffffffu, rm0, 2));
        rm1 = fmaxf(rm1, __shfl_xor_sync(0xffffffffu, rm1, 1));
        rm1 = fmaxf(rm1, __shfl_xor_sync(0xffffffffu, rm1, 2));

        float mn0 = fmaxf(m0v, rm0), mn1 = fmaxf(m1v, rm1);
        float f0 = exp2f(m0v - mn0), f1 = exp2f(m1v - mn1);

        float rs0 = 0.0f, rs1 = 0.0f;
        uint32_t aP[8][4];
        #pragma unroll
        for (int kk = 0; kk < 8; kk++) {
            float p00 = exp2f(s[2 * kk][0] - mn0);
            float p01 = exp2f(s[2 * kk][1] - mn0);
            float p02 = exp2f(s[2 * kk][2] - mn1);
            float p03 = exp2f(s[2 * kk][3] - mn1);
            float p10 = exp2f(s[2 * kk + 1][0] - mn0);
            float p11 = exp2f(s[2 * kk + 1][1] - mn0);
            float p12 = exp2f(s[2 * kk + 1][2] - mn1);
            float p13 = exp2f(s[2 * kk + 1][3] - mn1);
            rs0 += p00 + p01 + p10 + p11;
            rs1 += p02 + p03 + p12 + p13;
            aP[kk][0] = packh2(p00, p01);
            aP[kk][1] = packh2(p02, p03);
            aP[kk][2] = packh2(p10, p11);
            aP[kk][3] = packh2(p12, p13);
        }
        rs0 += __shfl_xor_sync(0xffffffffu, rs0, 1);
        rs0 += __shfl_xor_sync(0xffffffffu, rs0, 2);
        rs1 += __shfl_xor_sync(0xffffffffu, rs1, 1);
        rs1 += __shfl_xor_sync(0xffffffffu, rs1, 2);

        l0v = l0v * f0 + rs0;
        l1v = l1v * f1 + rs1;
        m0v = mn0; m1v = mn1;

        #pragma unroll
        for (int i = 0; i < 16; i++) {
            o[i][0] *= f0; o[i][1] *= f0;
            o[i][2] *= f1; o[i][3] *= f1;
        }

        #pragma unroll
        for (int djp = 0; djp < 8; djp++) {
            int dj = djp * 2 + hsel;
            int dc = dj >> 2, ks = dj & 3;
            #pragma unroll
            for (int kk = 0; kk < 8; kk++) {
                uint32_t vr[4];
                LDSM4T(vr, vb + dc * 8192 + swz_off(kk * 16 + r15, ks));
                MMAH(o[djp * 2],     aP[kk], vr[0], vr[1]);
                MMAH(o[djp * 2 + 1], aP[kk], vr[2], vr[3]);
            }
        }
    }

    float inv0 = 1.0f / l0v, inv1 = 1.0f / l1v;
    size_t base0 = (size_t)(b * SEQ + row_g0) * DMODEL + h * DHEAD;
    size_t base1 = base0 + (size_t)8 * DMODEL;
    #pragma unroll
    for (int djt = 0; djt < 16; djt++) {
        int col = djt * 8 + tq * 2;
        *(__half2*)(Z + base0 + col) = __floats2half2_rn(o[djt][0] * inv0, o[djt][1] * inv0);
        *(__half2*)(Z + base1 + col) = __floats2half2_rn(o[djt][2] * inv1, o[djt][3] * inv1);
    }
}

// ----------------------------------------------------------------------------
// Host launcher
// ----------------------------------------------------------------------------
extern "C" void kernel_launch(void* const* d_in, const int* in_sizes, int n_in,
                              void* d_out, int out_size) {
    const float* x    = (const float*)d_in[0];
    const float* fcos = (const float*)d_in[1];
    const float* fsin = (const float*)d_in[2];
    const float* wq   = (const float*)d_in[3];
    const float* wk   = (const float*)d_in[4];
    const float* wv   = (const float*)d_in[5];
    const float* wo   = (const float*)d_in[6];
    float* out = (float*)d_out;

    __half *x16, *wqkv, *wot, *z16, *q16, *k16, *v16;
    cudaGetSymbolAddress((void**)&x16, X16);
    cudaGetSymbolAddress((void**)&wqkv, WQKVT16);
    cudaGetSymbolAddress((void**)&wot, WOT16);
    cudaGetSymbolAddress((void**)&z16, Z16);
    cudaGetSymbolAddress((void**)&q16, Q16);
    cudaGetSymbolAddress((void**)&k16, K16);
    cudaGetSymbolAddress((void**)&v16, V16);

    cudaFuncSetAttribute(gemm_qkv, cudaFuncAttributeMaxDynamicSharedMemorySize, GEMM_SMEM);
    cudaFuncSetAttribute(wo_gemm, cudaFuncAttributeMaxDynamicSharedMemorySize, GEMM_SMEM);
    cudaFuncSetAttribute(flash_hmma, cudaFuncAttributeMaxDynamicSharedMemorySize, FLASH_SMEM);

    // All input conversions in ONE launch
    prep_all<<<PREP_JOBS, 256>>>(x, wq, wk, wv, wo, x16, wqkv, wot);

    // Merged QKV projection (single-pass fp16, fused RoPE epilogue)
    const float qs = 0.08838834764831845f * 1.4426950408889634f;   // scale * log2(e)
    gemm_qkv<<<dim3(QKVCOLS / GBN, MROWS / BM), 256, GEMM_SMEM>>>(
        x16, wqkv, fcos, fsin, q16, k16, v16, qs);

    // Flash attention (fp16 HMMA, 3-stage KV ring) -> Z16 fp16
    flash_hmma<<<dim3(SEQ / 128, BATCH * NHEAD), 256, FLASH_SMEM>>>(q16, k16, v16, z16);

    // Output projection: single-pass fp16
    wo_gemm<<<dim3(DMODEL / GBN, MROWS / BM), 256, GEMM_SMEM>>>(z16, wot, out, DMODEL, DMODEL);
}

// round 17
// speedup vs baseline: 1.0459x; 1.0459x over previous
#include <cuda_runtime.h>
#include <cuda_fp16.h>
#include <cstdint>
#include <math.h>

// Problem constants
#define BATCH 2
#define SEQ 2048
#define DMODEL 4096
#define NHEAD 32
#define NKVHEAD 8
#define DHEAD 128
#define MROWS (BATCH * SEQ)            // 4096
#define QCOLS (NHEAD * DHEAD)          // 4096
#define KVCOLS (NKVHEAD * DHEAD)       // 1024
#define QKVCOLS (QCOLS + 2 * KVCOLS)   // 6144

// ---------------------------------------------------------------------------
// Scratch buffers (__device__ globals; allocation-free rule)
// ---------------------------------------------------------------------------
__device__ __half X16[(size_t)MROWS * DMODEL];
__device__ __half WQKVT16[(size_t)QKVCOLS * DMODEL];  // rows: 0-4095 Q, 4096-5119 K, 5120-6143 V
__device__ __half WOT16[(size_t)DMODEL * DMODEL];
__device__ __half Z16[(size_t)MROWS * DMODEL];
__device__ __half Q16[(size_t)MROWS * QCOLS];
__device__ __half K16[(size_t)MROWS * KVCOLS];
__device__ __half V16[(size_t)MROWS * KVCOLS];

// ---------------------------------------------------------------------------
// Helpers
// ---------------------------------------------------------------------------
__device__ __forceinline__ uint32_t smem_u32(const void* p) {
    uint32_t a;
    asm("{ .reg .u64 t; cvta.to.shared.u64 t, %1; cvt.u32.u64 %0, t; }" : "=r"(a) : "l"(p));
    return a;
}

__device__ __forceinline__ void cp16(uint32_t dst, const void* src) {
    asm volatile("cp.async.cg.shared.global [%0], [%1], 16;" :: "r"(dst), "l"(src));
}
#define CP_COMMIT() asm volatile("cp.async.commit_group;" ::: "memory")
template <int N>
__device__ __forceinline__ void cp_wait() {
    asm volatile("cp.async.wait_group %0;" :: "n"(N) : "memory");
}

#define LDSM4(r, addr)                                                        \
    asm volatile("ldmatrix.sync.aligned.m8n8.x4.shared.b16 {%0,%1,%2,%3}, [%4];" \
        : "=r"((r)[0]), "=r"((r)[1]), "=r"((r)[2]), "=r"((r)[3]) : "r"(addr))

#define LDSM4T(r, addr)                                                       \
    asm volatile("ldmatrix.sync.aligned.m8n8.x4.trans.shared.b16 {%0,%1,%2,%3}, [%4];" \
        : "=r"((r)[0]), "=r"((r)[1]), "=r"((r)[2]), "=r"((r)[3]) : "r"(addr))

#define MMAH(c, a, b0, b1)                                                    \
    asm volatile("mma.sync.aligned.m16n8k16.row.col.f32.f16.f16.f32 "         \
        "{%0,%1,%2,%3}, {%4,%5,%6,%7}, {%8,%9}, {%0,%1,%2,%3};"               \
        : "+f"((c)[0]), "+f"((c)[1]), "+f"((c)[2]), "+f"((c)[3])              \
        : "r"((a)[0]), "r"((a)[1]), "r"((a)[2]), "r"((a)[3]),                 \
          "r"(b0), "r"(b1))

__device__ __forceinline__ uint32_t packh2(float x, float y) {
    __half2 h = __floats2half2_rn(x, y);
    return *(uint32_t*)&h;
}

// swizzled byte offset within a 64B-row tile for (row, kseg[0..3])
__device__ __forceinline__ uint32_t swz_off(int row, int ks) {
    return (uint32_t)(row * 64 + (((ks ^ (row >> 1)) & 3) << 4));
}

// ---------------------------------------------------------------------------
// prep_all: one launch: x fp32->fp16 convert + all 4 weight transposes.
// ---------------------------------------------------------------------------
#define X_JOBS 2048
#define WT_Q (64 * 128)
#define WT_K (64 * 32)
#define WT_V WT_K
#define WT_O (64 * 128)
#define PREP_JOBS (X_JOBS + WT_Q + WT_K + WT_V + WT_O)

__global__ __launch_bounds__(256) void prep_all(const float* __restrict__ x,
                                                const float* __restrict__ wq,
                                                const float* __restrict__ wk,
                                                const float* __restrict__ wv,
                                                const float* __restrict__ wo,
                                                __half* __restrict__ x16,
                                                __half* __restrict__ wqkv,
                                                __half* __restrict__ wot) {
    __shared__ float t[64][33];
    const int tid = threadIdx.x;
    int id = blockIdx.x;

    if (id < X_JOBS) {
        const float4* src = (const float4*)x + (size_t)id * 2048;
        uint4* dst = (uint4*)x16 + (size_t)id * 1024;
        #pragma unroll
        for (int u = 0; u < 4; u++) {
            int p = tid + u * 256;
            float4 a = src[2 * p];
            float4 b = src[2 * p + 1];
            uint4 o;
            o.x = packh2(a.x, a.y);
            o.y = packh2(a.z, a.w);
            o.z = packh2(b.x, b.y);
            o.w = packh2(b.z, b.w);
            dst[p] = o;
        }
        return;
    }
    id -= X_JOBS;

    const float* W;
    __half* T;
    int N;
    if (id < WT_Q)                { W = wq; T = wqkv;                                     N = QCOLS;  }
    else if (id < WT_Q + WT_K)    { W = wk; T = wqkv + (size_t)QCOLS * DMODEL;            N = KVCOLS; id -= WT_Q; }
    else if (id < WT_Q + WT_K + WT_V) { W = wv; T = wqkv + (size_t)(QCOLS + KVCOLS) * DMODEL; N = KVCOLS; id -= WT_Q + WT_K; }
    else                          { W = wo; T = wot;                                      N = DMODEL; id -= WT_Q + WT_K + WT_V; }

    const int ntx = N / 32;
    const int n0 = (id % ntx) * 32;
    const int k0 = (id / ntx) * 64;

    #pragma unroll
    for (int u = 0; u < 8; u++) {
        int idx = tid + u * 256;
        int row = idx >> 5, col = idx & 31;
        t[row][col] = W[(size_t)(k0 + row) * N + n0 + col];
    }
    __syncthreads();

    const int w = tid >> 5, lane = tid & 31;
    #pragma unroll
    for (int rr = 0; rr < 4; rr++) {
        int n = n0 + w * 4 + rr;
        __half2 v = __floats2half2_rn(t[lane * 2][w * 4 + rr],
                                      t[lane * 2 + 1][w * 4 + rr]);
        *(__half2*)(T + (size_t)n * DMODEL + k0 + lane * 2) = v;
    }
}

// ---------------------------------------------------------------------------
// GEMM config (R13): 256 threads, 8 warps (2x4), warp tile 64x32,
// BM=128, BN=128, BK=64/stage, NST=3, 98KB smem, 2 CTAs/SM.
// ---------------------------------------------------------------------------
#define BM 128
#define A32_B (BM * 32 * 2)                 // 8192
#define GBN 128
#define B32_B (GBN * 32 * 2)                // 8192
#define G_STAGE (2 * A32_B + 2 * B32_B)     // 32768
#define G_NST 3
#define GEMM_SMEM (G_NST * G_STAGE)         // 98304

// ---------------------------------------------------------------------------
// Merged QKV single-pass fp16 GEMM, fused RoPE/scale/head-major epilogue.
// grid (48, 32) = 1536 CTAs; 2 CTAs/SM.
// ---------------------------------------------------------------------------
__global__ __launch_bounds__(256, 2)
void gemm_qkv(const __half* __restrict__ A, const __half* __restrict__ B,
              const float* __restrict__ cosb, const float* __restrict__ sinb,
              __half* __restrict__ qo, __half* __restrict__ ko,
              __half* __restrict__ vo, float qs) {
    extern __shared__ char smem[];
    const uint32_t sb = smem_u32(smem);
    const int tid = threadIdx.x;
    const int wid = tid >> 5;
    const int lane = tid & 31;
    const int wm = wid >> 2;
    const int wn = wid & 3;
    const int m0 = blockIdx.y * BM;
    const int n0 = blockIdx.x * GBN;
    const int K = DMODEL;
    const int TOT = K / 64;

    float acc[4][4][4];
    #pragma unroll
    for (int i = 0; i < 4; i++)
        #pragma unroll
        for (int j = 0; j < 4; j++)
            #pragma unroll
            for (int r = 0; r < 4; r++) acc[i][j][r] = 0.0f;

    auto load_chunk = [&](int c, int s) {
        const __half* as = A + (size_t)m0 * K + c * 64;
        const __half* bs = B + (size_t)n0 * K + c * 64;
        uint32_t base = sb + s * G_STAGE;
        #pragma unroll
        for (int t = 0; t < 8; t++) {
            int idx = tid + t * 256;
            if (idx < 1024) {
                int kh = idx >> 9;
                int j = idx & 511;
                int row = j >> 2, ks = j & 3;
                cp16(base + kh * A32_B + swz_off(row, ks),
                     as + kh * 32 + (size_t)row * K + ks * 8);
            } else {
                int j = idx - 1024;
                int kh = j >> 9;
                int jj = j & 511;
                int row = jj >> 2, ks = jj & 3;
                cp16(base + 2 * A32_B + kh * B32_B + swz_off(row, ks),
                     bs + kh * 32 + (size_t)row * K + ks * 8);
            }
        }
    };

    load_chunk(0, 0); CP_COMMIT();
    load_chunk(1, 1); CP_COMMIT();

    const int r15 = lane & 15;
    const int hsel = lane >> 4;

    for (int c = 0; c < TOT; c++) {
        const int s = c % G_NST;
        cp_wait<1>();
        __syncthreads();

        {
            int nc = c + 2;
            if (nc < TOT) load_chunk(nc, nc % G_NST);
            CP_COMMIT();
        }

        const uint32_t ab0 = sb + s * G_STAGE;
        const uint32_t bb0 = ab0 + 2 * A32_B;

        #pragma unroll
        for (int kh = 0; kh < 2; kh++) {
            const uint32_t ab = ab0 + kh * A32_B;
            const uint32_t bb = bb0 + kh * B32_B;
            #pragma unroll
            for (int ks2 = 0; ks2 < 2; ks2++) {
                const int kseg = ks2 * 2 + hsel;
                uint32_t aF[4][4], bF[2][4];
                #pragma unroll
                for (int i = 0; i < 4; i++)
                    LDSM4(aF[i], ab + swz_off(wm * 64 + i * 16 + r15, kseg));
                #pragma unroll
                for (int j = 0; j < 2; j++)
                    LDSM4(bF[j], bb + swz_off(wn * 32 + j * 16 + r15, kseg));
                #pragma unroll
                for (int i = 0; i < 4; i++)
                    #pragma unroll
                    for (int j = 0; j < 2; j++) {
                        MMAH(acc[i][2 * j],     aF[i], bF[j][0], bF[j][2]);
                        MMAH(acc[i][2 * j + 1], aF[i], bF[j][1], bF[j][3]);
                    }
            }
        }
    }

    // Fused epilogue: CTA column block -> single head/region.
    const int quad = lane >> 2;
    const int tq = lane & 3;
    __half* dst;
    int H, c0;
    bool dorope;
    float scl;
    if (n0 < QCOLS)            { dst = qo; H = NHEAD;   c0 = n0;                 dorope = true;  scl = qs; }
    else if (n0 < QCOLS + 1024){ dst = ko; H = NKVHEAD; c0 = n0 - QCOLS;         dorope = true;  scl = 1.0f; }
    else                       { dst = vo; H = NKVHEAD; c0 = n0 - QCOLS - 1024;  dorope = false; scl = 1.0f; }
    const int h = c0 >> 7;

    #pragma unroll
    for (int i = 0; i < 4; i++) {
        int r0 = m0 + wm * 64 + i * 16 + quad;
        int b0 = r0 >> 11;
        int t0 = r0 & (SEQ - 1);
        #pragma unroll
        for (int j = 0; j < 4; j++) {
            int d = wn * 32 + j * 8 + tq * 2;
            int d2 = d >> 1;
            float f0 = acc[i][j][0], f1 = acc[i][j][1];
            float f2 = acc[i][j][2], f3 = acc[i][j][3];
            if (dorope) {
                float c0v = cosb[t0 * 64 + d2], s0v = sinb[t0 * 64 + d2];
                float c1v = cosb[(t0 + 8) * 64 + d2], s1v = sinb[(t0 + 8) * 64 + d2];
                float a0 = (f0 * c0v - f1 * s0v) * scl, a1 = (f0 * s0v + f1 * c0v) * scl;
                float a2 = (f2 * c1v - f3 * s1v) * scl, a3 = (f2 * s1v + f3 * c1v) * scl;
                f0 = a0; f1 = a1; f2 = a2; f3 = a3;
            }
            size_t o0 = (((size_t)b0 * H + h) * SEQ + t0) * DHEAD + d;
            *(__half2*)(dst + o0) = __floats2half2_rn(f0, f1);
            *(__half2*)(dst + o0 + (size_t)8 * DHEAD) = __floats2half2_rn(f2, f3);
        }
    }
}

// ---------------------------------------------------------------------------
// WO projection: single-pass fp16 GEMM (R13 config). 1024 CTAs.
// ---------------------------------------------------------------------------
__global__ __launch_bounds__(256, 2)
void wo_gemm(const __half* __restrict__ A, const __half* __restrict__ B,
             float* __restrict__ C, int N, int K) {
    extern __shared__ char smem[];
    const uint32_t sb = smem_u32(smem);
    const int tid = threadIdx.x;
    const int wid = tid >> 5;
    const int lane = tid & 31;
    const int wm = wid >> 2;
    const int wn = wid & 3;
    const int m0 = blockIdx.y * BM;
    const int n0 = blockIdx.x * GBN;
    const int TOT = K / 64;

    float acc[4][4][4];
    #pragma unroll
    for (int i = 0; i < 4; i++)
        #pragma unroll
        for (int j = 0; j < 4; j++)
            #pragma unroll
            for (int r = 0; r < 4; r++) acc[i][j][r] = 0.0f;

    auto load_chunk = [&](int c, int s) {
        const __half* as = A + (size_t)m0 * K + c * 64;
        const __half* bs = B + (size_t)n0 * K + c * 64;
        uint32_t base = sb + s * G_STAGE;
        #pragma unroll
        for (int t = 0; t < 8; t++) {
            int idx = tid + t * 256;
            if (idx < 1024) {
                int kh = idx >> 9;
                int j = idx & 511;
                int row = j >> 2, ks = j & 3;
                cp16(base + kh * A32_B + swz_off(row, ks),
                     as + kh * 32 + (size_t)row * K + ks * 8);
            } else {
                int j = idx - 1024;
                int kh = j >> 9;
                int jj = j & 511;
                int row = jj >> 2, ks = jj & 3;
                cp16(base + 2 * A32_B + kh * B32_B + swz_off(row, ks),
                     bs + kh * 32 + (size_t)row * K + ks * 8);
            }
        }
    };

    load_chunk(0, 0); CP_COMMIT();
    load_chunk(1, 1); CP_COMMIT();

    const int r15 = lane & 15;
    const int hsel = lane >> 4;

    for (int c = 0; c < TOT; c++) {
        const int s = c % G_NST;
        cp_wait<1>();
        __syncthreads();

        {
            int nc = c + 2;
            if (nc < TOT) load_chunk(nc, nc % G_NST);
            CP_COMMIT();
        }

        const uint32_t ab0 = sb + s * G_STAGE;
        const uint32_t bb0 = ab0 + 2 * A32_B;

        #pragma unroll
        for (int kh = 0; kh < 2; kh++) {
            const uint32_t ab = ab0 + kh * A32_B;
            const uint32_t bb = bb0 + kh * B32_B;
            #pragma unroll
            for (int ks2 = 0; ks2 < 2; ks2++) {
                const int kseg = ks2 * 2 + hsel;
                uint32_t aF[4][4], bF[2][4];
                #pragma unroll
                for (int i = 0; i < 4; i++)
                    LDSM4(aF[i], ab + swz_off(wm * 64 + i * 16 + r15, kseg));
                #pragma unroll
                for (int j = 0; j < 2; j++)
                    LDSM4(bF[j], bb + swz_off(wn * 32 + j * 16 + r15, kseg));
                #pragma unroll
                for (int i = 0; i < 4; i++)
                    #pragma unroll
                    for (int j = 0; j < 2; j++) {
                        MMAH(acc[i][2 * j],     aF[i], bF[j][0], bF[j][2]);
                        MMAH(acc[i][2 * j + 1], aF[i], bF[j][1], bF[j][3]);
                    }
            }
        }
    }

    const int quad = lane >> 2;
    const int tq = lane & 3;
    #pragma unroll
    for (int i = 0; i < 4; i++) {
        int row0 = m0 + wm * 64 + i * 16 + quad;
        #pragma unroll
        for (int j = 0; j < 4; j++) {
            int col = n0 + wn * 32 + j * 8 + tq * 2;
            *(float2*)(C + (size_t)row0 * N + col) =
                make_float2(acc[i][j][0], acc[i][j][1]);
            *(float2*)(C + (size_t)(row0 + 8) * N + col) =
                make_float2(acc[i][j][2], acc[i][j][3]);
        }
    }
}

// ----------------------------------------------------------------------------
// HMMA fp16 flash attention (R13 internals). grid (64, 16): x=bh, y maps to
// qt descending => globally heavy-first (LPT) scheduling.
// ----------------------------------------------------------------------------
#define QS_BYTES (128 * 128 * 2)
#define KV_BYTES (128 * 128 * 2)
#define FLASH_SMEM (QS_BYTES + 2 * (2 * KV_BYTES))   // 163840

__global__ __launch_bounds__(256, 1)
void flash_hmma(const __half* __restrict__ Qg, const __half* __restrict__ Kg,
                const __half* __restrict__ Vg, __half* __restrict__ Z) {
    extern __shared__ char smem[];
    const uint32_t sb = smem_u32(smem);
    const int tid = threadIdx.x;
    const int wid = tid >> 5;
    const int lane = tid & 31;
    const int quad = lane >> 2, tq = lane & 3;
    const int r15 = lane & 15, hsel = lane >> 4;
    const int qt = (gridDim.y - 1) - blockIdx.y;   // heavy q-tiles first (global LPT)
    const int q0 = qt * 128;
    const int bh = blockIdx.x;
    const int b = bh >> 5, h = bh & 31, kvh = h >> 2;
    const __half* qsrc = Qg + ((size_t)bh * SEQ + q0) * DHEAD;
    const __half* ksrc0 = Kg + ((size_t)(b * NKVHEAD + kvh)) * SEQ * DHEAD;
    const __half* vsrc0 = Vg + ((size_t)(b * NKVHEAD + kvh)) * SEQ * DHEAD;
    const int nkt = qt + 1;

    #pragma unroll
    for (int t = 0; t < 8; t++) {
        int j = tid + t * 256;
        int row = j >> 4, dc = (j >> 2) & 3, ks = j & 3;
        cp16(sb + dc * 8192 + swz_off(row, ks), qsrc + (size_t)row * DHEAD + dc * 32 + ks * 8);
    }
    CP_COMMIT();

    auto load_kv = [&](int t, int s) {
        uint32_t kb = sb + QS_BYTES + s * (2 * KV_BYTES);
        uint32_t vb = kb + KV_BYTES;
        const __half* ks_ = ksrc0 + (size_t)t * 128 * DHEAD;
        const __half* vs_ = vsrc0 + (size_t)t * 128 * DHEAD;
        #pragma unroll
        for (int u = 0; u < 16; u++) {
            int j = tid + u * 256;
            bool isv = j >= 2048;
            int jj = j & 2047;
            int row = jj >> 4, dc = (jj >> 2) & 3, ks = jj & 3;
            cp16((isv ? vb : kb) + dc * 8192 + swz_off(row, ks),
                 (isv ? vs_ : ks_) + (size_t)row * DHEAD + dc * 32 + ks * 8);
        }
    };

    load_kv(0, 0); CP_COMMIT();
    cp_wait<1>();
    __syncthreads();

    uint32_t qF[8][4];
    #pragma unroll
    for (int kc = 0; kc < 8; kc++) {
        int dc = kc >> 1;
        LDSM4(qF[kc], sb + dc * 8192 + swz_off(wid * 16 + r15, (kc & 1) * 2 + hsel));
    }

    if (nkt > 1) load_kv(1, 1);
    CP_COMMIT();

    float o[16][4];
    #pragma unroll
    for (int i = 0; i < 16; i++)
        #pragma unroll
        for (int r = 0; r < 4; r++) o[i][r] = 0.0f;
    float m0v = -1e30f, m1v = -1e30f, l0v = 0.0f, l1v = 0.0f;

    const int row_g0 = q0 + wid * 16 + quad;

    for (int t = 0; t < nkt; t++) {
        cp_wait<1>();
        __syncthreads();
        const uint32_t kb = sb + QS_BYTES + (t & 1) * (2 * KV_BYTES);
        const uint32_t vb = kb + KV_BYTES;

        float s[16][4];
        #pragma unroll
        for (int j = 0; j < 16; j++)
            #pragma unroll
            for (int r = 0; r < 4; r++) s[j][r] = 0.0f;

        #pragma unroll
        for (int kc = 0; kc < 8; kc++) {
            int dc = kc >> 1;
            #pragma unroll
            for (int j = 0; j < 8; j++) {
                uint32_t kf[4];
                LDSM4(kf, kb + dc * 8192 + swz_off(j * 16 + r15, (kc & 1) * 2 + hsel));
                MMAH(s[2 * j],     qF[kc], kf[0], kf[2]);
                MMAH(s[2 * j + 1], qF[kc], kf[1], kf[3]);
            }
        }

        if (t == nkt - 1) {
            #pragma unroll
            for (int j = 0; j < 16; j++) {
                int col = t * 128 + j * 8 + tq * 2;
                if (col     > row_g0)     s[j][0] = -1e30f;
                if (col + 1 > row_g0)     s[j][1] = -1e30f;
                if (col     > row_g0 + 8) s[j][2] = -1e30f;
                if (col + 1 > row_g0 + 8) s[j][3] = -1e30f;
            }
        }

        float rm0 = -1e30f, rm1 = -1e30f;
        #pragma unroll
        for (int j = 0; j < 16; j++) {
            rm0 = fmaxf(rm0, fmaxf(s[j][0], s[j][1]));
            rm1 = fmaxf(rm1, fmaxf(s[j][2], s[j][3]));
        }
        rm0 = fmaxf(rm0, __shfl_xor_sync(0xffffffffu, rm0, 1));
        rm0 = fmaxf(rm0, __shfl_xor_sync(0xffffffffu, rm0, 2));
        rm1 = fmaxf(rm1, __shfl_xor_sync(0xffffffffu, rm1, 1));
        rm1 = fmaxf(rm1, __shfl_xor_sync(0xffffffffu, rm1, 2));

        float mn0 = fmaxf(m0v, rm0), mn1 = fmaxf(m1v, rm1);
        float f0 = exp2f(m0v - mn0), f1 = exp2f(m1v - mn1);

        float rs0 = 0.0f, rs1 = 0.0f;
        uint32_t aP[8][4];
        #pragma unroll
        for (int kk = 0; kk < 8; kk++) {
            float p00 = exp2f(s[2 * kk][0] - mn0);
            float p01 = exp2f(s[2 * kk][1] - mn0);
            float p02 = exp2f(s[2 * kk][2] - mn1);
            float p03 = exp2f(s[2 * kk][3] - mn1);
            float p10 = exp2f(s[2 * kk + 1][0] - mn0);
            float p11 = exp2f(s[2 * kk + 1][1] - mn0);
            float p12 = exp2f(s[2 * kk + 1][2] - mn1);
            float p13 = exp2f(s[2 * kk + 1][3] - mn1);
            rs0 += p00 + p01 + p10 + p11;
            rs1 += p02 + p03 + p12 + p13;
            aP[kk][0] = packh2(p00, p01);
            aP[kk][1] = packh2(p02, p03);
            aP[kk][2] = packh2(p10, p11);
            aP[kk][3] = packh2(p12, p13);
        }
        rs0 += __shfl_xor_sync(0xffffffffu, rs0, 1);
        rs0 += __shfl_xor_sync(0xffffffffu, rs0, 2);
        rs1 += __shfl_xor_sync(0xffffffffu, rs1, 1);
        rs1 += __shfl_xor_sync(0xffffffffu, rs1, 2);

        l0v = l0v * f0 + rs0;
        l1v = l1v * f1 + rs1;
        m0v = mn0; m1v = mn1;

        #pragma unroll
        for (int i = 0; i < 16; i++) {
            o[i][0] *= f0; o[i][1] *= f0;
            o[i][2] *= f1; o[i][3] *= f1;
        }

        #pragma unroll
        for (int djp = 0; djp < 8; djp++) {
            int dj = djp * 2 + hsel;
            int dc = dj >> 2, ks = dj & 3;
            #pragma unroll
            for (int kk = 0; kk < 8; kk++) {
                uint32_t vr[4];
                LDSM4T(vr, vb + dc * 8192 + swz_off(kk * 16 + r15, ks));
                MMAH(o[djp * 2],     aP[kk], vr[0], vr[1]);
                MMAH(o[djp * 2 + 1], aP[kk], vr[2], vr[3]);
            }
        }

        __syncthreads();
        if (t + 2 < nkt) load_kv(t + 2, t & 1);
        CP_COMMIT();
    }

    float inv0 = 1.0f / l0v, inv1 = 1.0f / l1v;
    size_t base0 = (size_t)(b * SEQ + row_g0) * DMODEL + h * DHEAD;
    size_t base1 = base0 + (size_t)8 * DMODEL;
    #pragma unroll
    for (int djt = 0; djt < 16; djt++) {
        int col = djt * 8 + tq * 2;
        *(__half2*)(Z + base0 + col) = __floats2half2_rn(o[djt][0] * inv0, o[djt][1] * inv0);
        *(__half2*)(Z + base1 + col) = __floats2half2_rn(o[djt][2] * inv1, o[djt][3] * inv1);
    }
}

// ----------------------------------------------------------------------------
// Host launcher
// ----------------------------------------------------------------------------
extern "C" void kernel_launch(void* const* d_in, const int* in_sizes, int n_in,
                              void* d_out, int out_size) {
    const float* x    = (const float*)d_in[0];
    const float* fcos = (const float*)d_in[1];
    const float* fsin = (const float*)d_in[2];
    const float* wq   = (const float*)d_in[3];
    const float* wk   = (const float*)d_in[4];
    const float* wv   = (const float*)d_in[5];
    const float* wo   = (const float*)d_in[6];
    float* out = (float*)d_out;

    __half *x16, *wqkv, *wot, *z16, *q16, *k16, *v16;
    cudaGetSymbolAddress((void**)&x16, X16);
    cudaGetSymbolAddress((void**)&wqkv, WQKVT16);
    cudaGetSymbolAddress((void**)&wot, WOT16);
    cudaGetSymbolAddress((void**)&z16, Z16);
    cudaGetSymbolAddress((void**)&q16, Q16);
    cudaGetSymbolAddress((void**)&k16, K16);
    cudaGetSymbolAddress((void**)&v16, V16);

    cudaFuncSetAttribute(gemm_qkv, cudaFuncAttributeMaxDynamicSharedMemorySize, GEMM_SMEM);
    cudaFuncSetAttribute(wo_gemm, cudaFuncAttributeMaxDynamicSharedMemorySize, GEMM_SMEM);
    cudaFuncSetAttribute(flash_hmma, cudaFuncAttributeMaxDynamicSharedMemorySize, FLASH_SMEM);

    // All input conversions in ONE launch
    prep_all<<<PREP_JOBS, 256>>>(x, wq, wk, wv, wo, x16, wqkv, wot);

    // Merged QKV projection (single-pass fp16, fused RoPE epilogue)
    const float qs = 0.08838834764831845f * 1.4426950408889634f;   // scale * log2(e)
    gemm_qkv<<<dim3(QKVCOLS / GBN, MROWS / BM), 256, GEMM_SMEM>>>(
        x16, wqkv, fcos, fsin, q16, k16, v16, qs);

    // Flash attention (fp16 HMMA) -> Z16 fp16; grid x=bh, y=qt (LPT order)
    flash_hmma<<<dim3(BATCH * NHEAD, SEQ / 128), 256, FLASH_SMEM>>>(q16, k16, v16, z16);

    // Output projection: single-pass fp16
    wo_gemm<<<dim3(DMODEL / GBN, MROWS / BM), 256, GEMM_SMEM>>>(z16, wot, out, DMODEL, DMODEL);
}